// round 5
// baseline (speedup 1.0000x reference)
#include <cuda_runtime.h>
#include <math.h>

#define BS      4096
#define NE      6
#define D_FRAME 1830
#define D_I     1027
#define D_HH    512
#define D_P     2086
#define D_HEAD  1830   // 330 + 3 + 297 + 1200 packed head output

// ---------------- scratch (static device memory; no allocation) ----------------
__device__ float g_h0  [BS * D_P];      // [frame_prev (1830) | I_feat (256)]
__device__ float g_Iin [BS * D_I];
__device__ float g_t1  [BS * 256];
__device__ float g_t2  [BS * 256];
__device__ float g_g1  [BS * 512];
__device__ float g_g2  [BS * 256];
__device__ float g_om  [BS * NE];
__device__ float g_ha  [BS * D_HH];
__device__ float g_hb  [BS * D_HH];
__device__ float g_Wc  [D_HH * D_HEAD];
__device__ float g_bc  [D_HEAD];
__device__ float g_head[BS * D_HEAD];

// ---------------- helpers ----------------
__device__ __forceinline__ float eluf(float x) { return x > 0.f ? x : expm1f(x); }

__device__ __forceinline__ unsigned long long ffma2(unsigned long long a,
                                                    unsigned long long b,
                                                    unsigned long long c) {
    unsigned long long d;
    asm("fma.rn.f32x2 %0, %1, %2, %3;" : "=l"(d) : "l"(a), "l"(b), "l"(c));
    return d;
}
__device__ __forceinline__ unsigned long long dup2(float b) {
    unsigned long long r;
    asm("mov.b64 %0, {%1, %1};" : "=l"(r) : "f"(b));
    return r;
}
__device__ __forceinline__ void unpack2(unsigned long long v, float& lo, float& hi) {
    asm("mov.b64 {%0, %1}, %2;" : "=f"(lo), "=f"(hi) : "l"(v));
}

// ---------------- input assembly ----------------
__global__ void build_frame(const float* __restrict__ ppr,   // (BS,1,55,9)
                            const float* __restrict__ transl,// (BS,3)
                            const float* __restrict__ verts, // (BS,400,3)
                            const float* __restrict__ dists) // (BS,99,3)
{
    int idx = blockIdx.x * blockDim.x + threadIdx.x;
    if (idx >= BS * D_FRAME) return;
    int b = idx / D_FRAME;
    int c = idx - b * D_FRAME;
    float v;
    if (c < 330) {
        int j = c / 6, r = c - j * 6;
        // rotmat indices for [..., :2] of 3x3: 0,1,3,4,6,7
        int map = r + (r >> 1);            // 0,1,3,4,6,7
        v = ppr[b * 495 + j * 9 + map];
    } else if (c < 333) {
        v = transl[b * 3 + (c - 330)];
    } else if (c < 1533) {
        v = verts[b * 1200 + (c - 333)];
    } else {
        v = dists[b * 297 + (c - 1533)];
    }
    g_h0[b * D_P + c] = v;
}

__global__ void build_iin(const float* __restrict__ bps,  // (BS,1024)
                          const float* __restrict__ ogt)  // (BS,3)
{
    int idx = blockIdx.x * blockDim.x + threadIdx.x;
    if (idx >= BS * D_I) return;
    int b = idx / D_I;
    int c = idx - b * D_I;
    g_Iin[idx] = (c < 1024) ? bps[b * 1024 + c] : ogt[b * 3 + (c - 1024)];
}

// ---------------- generic GEMM: C = act(A @ B + bias) ----------------
// A: (4096, K) with leading dim lda (row-major); B: (K, N) row-major.
// BM=128, BN=64, BK=16, 128 threads, per-thread micro-tile 8(M) x 8(N),
// M-pairs packed in f32x2 (FFMA2 doubles fp32 throughput on sm_103a).
#define GBM 128
#define GBN 64
#define GBK 16

__global__ __launch_bounds__(128)
void gemm_bias_act(const float* __restrict__ A, int lda,
                   const float* __restrict__ B,
                   const float* __restrict__ bias,
                   float* __restrict__ C, int ldc,
                   int N, int K, int act)
{
    __shared__ __align__(16) float As[GBK][GBM + 2];
    __shared__ __align__(16) float Bs[GBK][GBN];

    const int t  = threadIdx.x;
    const int tx = t & 7;       // 8 col-groups
    const int ty = t >> 3;      // 16 row-groups
    const int m0 = blockIdx.y * GBM;
    const int n0 = blockIdx.x * GBN;

    unsigned long long acc[4][8];
#pragma unroll
    for (int p = 0; p < 4; p++)
#pragma unroll
        for (int j = 0; j < 8; j++) acc[p][j] = 0ull;

    for (int kk0 = 0; kk0 < K; kk0 += GBK) {
        // A tile: 128x16, coalesced (16 consecutive k per row-group)
#pragma unroll
        for (int i = 0; i < 16; i++) {
            int l = i * 128 + t;
            int m = l >> 4, k = l & 15;
            int kg = kk0 + k;
            As[k][m] = (kg < K) ? A[(m0 + m) * lda + kg] : 0.f;
        }
        // B tile: 16x64, fully coalesced along n
#pragma unroll
        for (int i = 0; i < 8; i++) {
            int l = i * 128 + t;
            int n = l & 63, k = l >> 6;
            int kg = kk0 + k, ng = n0 + n;
            Bs[k][n] = (kg < K && ng < N) ? B[kg * N + ng] : 0.f;
        }
        __syncthreads();

#pragma unroll
        for (int k = 0; k < GBK; k++) {
            unsigned long long a2[4];
#pragma unroll
            for (int p = 0; p < 4; p++)
                a2[p] = *(const unsigned long long*)&As[k][ty * 8 + 2 * p];
            float4 b0 = *(const float4*)&Bs[k][tx * 8];
            float4 b1 = *(const float4*)&Bs[k][tx * 8 + 4];
            float bv[8] = {b0.x, b0.y, b0.z, b0.w, b1.x, b1.y, b1.z, b1.w};
#pragma unroll
            for (int j = 0; j < 8; j++) {
                unsigned long long bb = dup2(bv[j]);
#pragma unroll
                for (int p = 0; p < 4; p++)
                    acc[p][j] = ffma2(a2[p], bb, acc[p][j]);
            }
        }
        __syncthreads();
    }

#pragma unroll
    for (int p = 0; p < 4; p++) {
        int m = m0 + ty * 8 + 2 * p;
#pragma unroll
        for (int j = 0; j < 8; j++) {
            int n = n0 + tx * 8 + j;
            if (n < N) {
                float lo, hi;
                unpack2(acc[p][j], lo, hi);
                float bsv = bias[n];
                lo += bsv; hi += bsv;
                if (act) { lo = eluf(lo); hi = eluf(hi); }
                C[m * ldc + n]       = lo;
                C[(m + 1) * ldc + n] = hi;
            }
        }
    }
}

// ---------------- MoE GEMM over stacked experts ----------------
// C[b,n] = elu( sum_e om[b,e] * (A[b,:] @ W_e)[n]  +  sum_e om[b,e]*eb[e,n] )
// Implemented as a single GEMM with K_tot = 6*Kper: the expert bank (E,K,N) is
// contiguous, so B rows index directly by stacked k; only A needs (e,i) decode
// and on-the-fly scaling by om[b,e].
__global__ __launch_bounds__(128)
void moe_gemm(const float* __restrict__ A, int lda,
              const float* __restrict__ W,     // (NE*Kper, N) contiguous
              const float* __restrict__ eb,    // (NE, N)
              const float* __restrict__ om,    // (BS, NE)
              float* __restrict__ C,
              int N, int Kper)
{
    __shared__ __align__(16) float As[GBK][GBM + 2];
    __shared__ __align__(16) float Bs[GBK][GBN];
    __shared__ float om_s[GBM * NE];

    const int t  = threadIdx.x;
    const int tx = t & 7;
    const int ty = t >> 3;
    const int m0 = blockIdx.y * GBM;
    const int n0 = blockIdx.x * GBN;
    const int Ktot = NE * Kper;

    for (int i = t; i < GBM * NE; i += 128) om_s[i] = om[m0 * NE + i];
    __syncthreads();

    unsigned long long acc[4][8];
#pragma unroll
    for (int p = 0; p < 4; p++)
#pragma unroll
        for (int j = 0; j < 8; j++) acc[p][j] = 0ull;

    for (int kk0 = 0; kk0 < Ktot; kk0 += GBK) {
        int e0 = kk0 / Kper;
        int r0 = kk0 - e0 * Kper;   // tile straddles at most one expert boundary
#pragma unroll
        for (int i = 0; i < 16; i++) {
            int l = i * 128 + t;
            int m = l >> 4, k = l & 15;
            int kg = kk0 + k;
            float v = 0.f;
            if (kg < Ktot) {
                int e = e0, ii = r0 + k;
                if (ii >= Kper) { ii -= Kper; e++; }
                v = A[(m0 + m) * lda + ii] * om_s[m * NE + e];
            }
            As[k][m] = v;
        }
#pragma unroll
        for (int i = 0; i < 8; i++) {
            int l = i * 128 + t;
            int n = l & 63, k = l >> 6;
            int kg = kk0 + k, ng = n0 + n;
            Bs[k][n] = (kg < Ktot && ng < N) ? W[kg * N + ng] : 0.f;
        }
        __syncthreads();

#pragma unroll
        for (int k = 0; k < GBK; k++) {
            unsigned long long a2[4];
#pragma unroll
            for (int p = 0; p < 4; p++)
                a2[p] = *(const unsigned long long*)&As[k][ty * 8 + 2 * p];
            float4 b0 = *(const float4*)&Bs[k][tx * 8];
            float4 b1 = *(const float4*)&Bs[k][tx * 8 + 4];
            float bv[8] = {b0.x, b0.y, b0.z, b0.w, b1.x, b1.y, b1.z, b1.w};
#pragma unroll
            for (int j = 0; j < 8; j++) {
                unsigned long long bb = dup2(bv[j]);
#pragma unroll
                for (int p = 0; p < 4; p++)
                    acc[p][j] = ffma2(a2[p], bb, acc[p][j]);
            }
        }
        __syncthreads();
    }

#pragma unroll
    for (int p = 0; p < 4; p++) {
        int ml = ty * 8 + 2 * p;
        int m  = m0 + ml;
#pragma unroll
        for (int j = 0; j < 8; j++) {
            int n = n0 + tx * 8 + j;
            if (n < N) {
                float lo, hi;
                unpack2(acc[p][j], lo, hi);
                float blo = 0.f, bhi = 0.f;
#pragma unroll
                for (int e = 0; e < NE; e++) {
                    float ev = eb[e * N + n];
                    blo += om_s[ml * NE + e] * ev;
                    bhi += om_s[(ml + 1) * NE + e] * ev;
                }
                C[m * N + n]       = eluf(lo + blo);
                C[(m + 1) * N + n] = eluf(hi + bhi);
            }
        }
    }
}

// ---------------- gating layer 3 + softmax (K=256, N=6) ----------------
__global__ void gate3_softmax(const float* __restrict__ g2,
                              const float* __restrict__ gw3,
                              const float* __restrict__ gb3,
                              float* __restrict__ om)
{
    int gwarp = (blockIdx.x * blockDim.x + threadIdx.x) >> 5;
    int lane  = threadIdx.x & 31;
    if (gwarp >= BS) return;
    float s[NE] = {0, 0, 0, 0, 0, 0};
    for (int k = lane; k < 256; k += 32) {
        float v = g2[gwarp * 256 + k];
#pragma unroll
        for (int o = 0; o < NE; o++) s[o] += v * gw3[k * NE + o];
    }
#pragma unroll
    for (int o = 0; o < NE; o++)
#pragma unroll
        for (int off = 16; off; off >>= 1)
            s[o] += __shfl_xor_sync(0xffffffffu, s[o], off);
    if (lane == 0) {
        float mx = -1e30f;
#pragma unroll
        for (int o = 0; o < NE; o++) { s[o] += gb3[o]; mx = fmaxf(mx, s[o]); }
        float sum = 0.f;
#pragma unroll
        for (int o = 0; o < NE; o++) { s[o] = expf(s[o] - mx); sum += s[o]; }
        float inv = 1.f / sum;
#pragma unroll
        for (int o = 0; o < NE; o++) om[gwarp * NE + o] = s[o] * inv;
    }
}

// ---------------- pack 4 head weight matrices into one (512 x 1830) ----------------
__global__ void pack_heads(const float* __restrict__ pw, const float* __restrict__ pb,
                           const float* __restrict__ tw, const float* __restrict__ tb,
                           const float* __restrict__ dw, const float* __restrict__ db,
                           const float* __restrict__ vw, const float* __restrict__ vb)
{
    int idx = blockIdx.x * blockDim.x + threadIdx.x;
    if (idx >= D_HH * D_HEAD) return;
    int k = idx / D_HEAD;
    int n = idx - k * D_HEAD;
    float w;
    if      (n < 330) w = pw[k * 330 + n];
    else if (n < 333) w = tw[k * 3 + (n - 330)];
    else if (n < 630) w = dw[k * 297 + (n - 333)];
    else              w = vw[k * 1200 + (n - 630)];
    g_Wc[idx] = w;
    if (idx < D_HEAD) {
        float b;
        if      (idx < 330) b = pb[idx];
        else if (idx < 333) b = tb[idx - 330];
        else if (idx < 630) b = db[idx - 333];
        else                b = vb[idx - 630];
        g_bc[idx] = b;
    }
}

// ---------------- finalize: crot2rotmat + scatter to output layout ----------------
__global__ void finalize(float* __restrict__ out)
{
    const int b   = blockIdx.x;
    const int tid = threadIdx.x;
    const float* h = &g_head[b * D_HEAD];
    const long long T0 = (long long)BS * 495;
    const long long D0 = T0 + (long long)BS * 3;
    const long long V0 = D0 + (long long)BS * 297;

    if (tid < 55) {
        const float* p = h + tid * 6;
        float a1x = p[0], a2x = p[1];
        float a1y = p[2], a2y = p[3];
        float a1z = p[4], a2z = p[5];
        float inv1 = 1.f / sqrtf(a1x * a1x + a1y * a1y + a1z * a1z);
        float b1x = a1x * inv1, b1y = a1y * inv1, b1z = a1z * inv1;
        float d = b1x * a2x + b1y * a2y + b1z * a2z;
        float cx = a2x - d * b1x, cy = a2y - d * b1y, cz = a2z - d * b1z;
        float inv2 = 1.f / sqrtf(cx * cx + cy * cy + cz * cz);
        float b2x = cx * inv2, b2y = cy * inv2, b2z = cz * inv2;
        float b3x = b1y * b2z - b1z * b2y;
        float b3y = b1z * b2x - b1x * b2z;
        float b3z = b1x * b2y - b1y * b2x;
        float* o = out + (long long)b * 495 + tid * 9;
        o[0] = b1x; o[1] = b2x; o[2] = b3x;
        o[3] = b1y; o[4] = b2y; o[5] = b3y;
        o[6] = b1z; o[7] = b2z; o[8] = b3z;
    }
    for (int c = tid; c < 3; c += blockDim.x)
        out[T0 + (long long)b * 3 + c] = h[330 + c];
    for (int c = tid; c < 297; c += blockDim.x)
        out[D0 + (long long)b * 297 + c] = h[333 + c];
    for (int c = tid; c < 1200; c += blockDim.x)
        out[V0 + (long long)b * 1200 + c] = h[630 + c];
}

// ---------------- host launcher ----------------
extern "C" void kernel_launch(void* const* d_in, const int* in_sizes, int n_in,
                              void* d_out, int out_size)
{
    const float* ppr    = (const float*)d_in[0];
    const float* transl = (const float*)d_in[1];
    const float* verts  = (const float*)d_in[2];
    const float* dists  = (const float*)d_in[3];
    const float* bps    = (const float*)d_in[4];
    const float* ogt    = (const float*)d_in[5];
    const float* iw1 = (const float*)d_in[6];  const float* ib1 = (const float*)d_in[7];
    const float* iw2 = (const float*)d_in[8];  const float* ib2 = (const float*)d_in[9];
    const float* iw3 = (const float*)d_in[10]; const float* ib3 = (const float*)d_in[11];
    const float* gw1 = (const float*)d_in[12]; const float* gb1 = (const float*)d_in[13];
    const float* gw2 = (const float*)d_in[14]; const float* gb2 = (const float*)d_in[15];
    const float* gw3 = (const float*)d_in[16]; const float* gb3 = (const float*)d_in[17];
    const float* ew1 = (const float*)d_in[18]; const float* eb1 = (const float*)d_in[19];
    const float* ew2 = (const float*)d_in[20]; const float* eb2 = (const float*)d_in[21];
    const float* ew3 = (const float*)d_in[22]; const float* eb3 = (const float*)d_in[23];
    const float* pw  = (const float*)d_in[24]; const float* pb  = (const float*)d_in[25];
    const float* tw  = (const float*)d_in[26]; const float* tb  = (const float*)d_in[27];
    const float* vw  = (const float*)d_in[28]; const float* vb  = (const float*)d_in[29];
    const float* dw  = (const float*)d_in[30]; const float* db  = (const float*)d_in[31];
    float* out = (float*)d_out;

    float *h0, *Iin, *t1, *t2, *g1, *g2, *om, *ha, *hb, *Wc, *bc, *head;
    cudaGetSymbolAddress((void**)&h0,   g_h0);
    cudaGetSymbolAddress((void**)&Iin,  g_Iin);
    cudaGetSymbolAddress((void**)&t1,   g_t1);
    cudaGetSymbolAddress((void**)&t2,   g_t2);
    cudaGetSymbolAddress((void**)&g1,   g_g1);
    cudaGetSymbolAddress((void**)&g2,   g_g2);
    cudaGetSymbolAddress((void**)&om,   g_om);
    cudaGetSymbolAddress((void**)&ha,   g_ha);
    cudaGetSymbolAddress((void**)&hb,   g_hb);
    cudaGetSymbolAddress((void**)&Wc,   g_Wc);
    cudaGetSymbolAddress((void**)&bc,   g_bc);
    cudaGetSymbolAddress((void**)&head, g_head);

    const int MB = BS / GBM;  // 32 row-blocks

    build_frame<<<(BS * D_FRAME + 255) / 256, 256>>>(ppr, transl, verts, dists);
    build_iin  <<<(BS * D_I + 255) / 256, 256>>>(bps, ogt);
    pack_heads <<<(D_HH * D_HEAD + 255) / 256, 256>>>(pw, pb, tw, tb, dw, db, vw, vb);

    // INet: 1027 -> 256 -> 256 -> 256 (last writes into h0 cols [1830,2086))
    gemm_bias_act<<<dim3(4, MB), 128>>>(Iin, D_I, iw1, ib1, t1, 256, 256, D_I, 1);
    gemm_bias_act<<<dim3(4, MB), 128>>>(t1, 256, iw2, ib2, t2, 256, 256, 256, 1);
    gemm_bias_act<<<dim3(4, MB), 128>>>(t2, 256, iw3, ib3, h0 + D_FRAME, D_P, 256, 256, 1);

    // Gating: 1830 -> 512 -> 256 -> 6 + softmax
    gemm_bias_act<<<dim3(8, MB), 128>>>(h0, D_P, gw1, gb1, g1, 512, 512, D_FRAME, 1);
    gemm_bias_act<<<dim3(4, MB), 128>>>(g1, 512, gw2, gb2, g2, 256, 256, 512, 1);
    gate3_softmax<<<BS / 8, 256>>>(g2, gw3, gb3, om);

    // MoE trunk: 3 stacked-expert GEMMs
    moe_gemm<<<dim3(8, MB), 128>>>(h0, D_P, ew1, eb1, om, ha, D_HH, D_P);
    moe_gemm<<<dim3(8, MB), 128>>>(ha, D_HH, ew2, eb2, om, hb, D_HH, D_HH);
    moe_gemm<<<dim3(8, MB), 128>>>(hb, D_HH, ew3, eb3, om, ha, D_HH, D_HH);

    // Fused heads: 4096 x 1830 = (4096 x 512) @ (512 x 1830)
    gemm_bias_act<<<dim3((D_HEAD + GBN - 1) / GBN, MB), 128>>>(
        ha, D_HH, Wc, bc, head, D_HEAD, D_HEAD, D_HH, 0);

    finalize<<<BS, 128>>>(out);
}